// round 3
// baseline (speedup 1.0000x reference)
#include <cuda_runtime.h>
#include <cstdint>

// out[src] += feat[dst] * w    ; feat [N,64] f32, E=1e6, N=1e5
// Strategy: build CSR by src each call (hist + scan + scatter), then
// atomic-free per-node accumulation (16 lanes/node, float4 gather + FMA).
//
// Inputs: d_in[0]=feat f32[N*64], d_in[1]=ew f32[E],
//         d_in[2]=esrc i32[E],    d_in[3]=edst i32[E]

#define MAXN 100000
#define MAXE 1000000
#define SCAN_CHUNK 1024
#define MAXNB 128   // ceil(MAXN/SCAN_CHUNK) = 98

__device__ int   g_cnt[MAXN];
__device__ int   g_start[MAXN];
__device__ int   g_cursor[MAXN];
__device__ int   g_pdst[MAXE];
__device__ float g_pw[MAXE];
__device__ int   g_bsum[MAXNB];
__device__ int   g_boff[MAXNB];

__global__ void k_zero_cnt(int n) {
    int i = blockIdx.x * blockDim.x + threadIdx.x;
    if (i < n) g_cnt[i] = 0;
}

__global__ void k_hist(const int* __restrict__ esrc, int n_edges) {
    int i = blockIdx.x * blockDim.x + threadIdx.x;
    if (i < n_edges) atomicAdd(&g_cnt[esrc[i]], 1);
}

// one block per SCAN_CHUNK: sum counts of the chunk
__global__ void k_bsum(int n) {
    __shared__ int sh[256];
    int b = blockIdx.x, t = threadIdx.x;
    int base = b * SCAN_CHUNK;
    int v = 0;
    for (int k = t; k < SCAN_CHUNK; k += 256) {
        int i = base + k;
        if (i < n) v += g_cnt[i];
    }
    sh[t] = v; __syncthreads();
    for (int off = 128; off > 0; off >>= 1) {
        if (t < off) sh[t] += sh[t + off];
        __syncthreads();
    }
    if (t == 0) g_bsum[b] = sh[0];
}

// exclusive scan of per-chunk sums (tiny, single thread)
__global__ void k_scanb(int nb) {
    int run = 0;
    for (int b = 0; b < nb; b++) { g_boff[b] = run; run += g_bsum[b]; }
}

// per-chunk exclusive scan -> g_start / g_cursor
__global__ __launch_bounds__(SCAN_CHUNK) void k_offsets(int n) {
    __shared__ int s[SCAN_CHUNK];
    int b = blockIdx.x, t = threadIdx.x;
    int i = b * SCAN_CHUNK + t;
    int v = (i < n) ? g_cnt[i] : 0;
    s[t] = v; __syncthreads();
    for (int off = 1; off < SCAN_CHUNK; off <<= 1) {
        int x = (t >= off) ? s[t - off] : 0;
        __syncthreads();
        s[t] += x;
        __syncthreads();
    }
    if (i < n) {
        int start = g_boff[b] + s[t] - v;   // exclusive
        g_start[i]  = start;
        g_cursor[i] = start;
    }
}

__global__ void k_scatter(const int* __restrict__ esrc,
                          const int* __restrict__ edst,
                          const float* __restrict__ ew,
                          int n_edges) {
    int i = blockIdx.x * blockDim.x + threadIdx.x;
    if (i >= n_edges) return;
    int s = esrc[i];
    int pos = atomicAdd(&g_cursor[s], 1);
    g_pdst[pos] = edst[i];
    g_pw[pos]   = ew[i];
}

// 16 lanes per node: gather rows of feat for this node's edge list, FMA, store once.
__global__ __launch_bounds__(256) void k_accum(const float* __restrict__ feat,
                                               float* __restrict__ out,
                                               int n_nodes) {
    int gid   = blockIdx.x * blockDim.x + threadIdx.x;
    int node  = gid >> 4;
    int lane  = gid & 15;
    if (node >= n_nodes) return;

    int beg = g_start[node];
    int end = beg + g_cnt[node];

    float4 acc = make_float4(0.f, 0.f, 0.f, 0.f);
    int j = beg;
    for (; j + 1 < end; j += 2) {
        int   d0 = __ldg(&g_pdst[j]);
        int   d1 = __ldg(&g_pdst[j + 1]);
        float w0 = __ldg(&g_pw[j]);
        float w1 = __ldg(&g_pw[j + 1]);
        float4 v0 = __ldg(&reinterpret_cast<const float4*>(feat + (long long)d0 * 64)[lane]);
        float4 v1 = __ldg(&reinterpret_cast<const float4*>(feat + (long long)d1 * 64)[lane]);
        acc.x += v0.x * w0 + v1.x * w1;
        acc.y += v0.y * w0 + v1.y * w1;
        acc.z += v0.z * w0 + v1.z * w1;
        acc.w += v0.w * w0 + v1.w * w1;
    }
    if (j < end) {
        int   d0 = __ldg(&g_pdst[j]);
        float w0 = __ldg(&g_pw[j]);
        float4 v0 = __ldg(&reinterpret_cast<const float4*>(feat + (long long)d0 * 64)[lane]);
        acc.x += v0.x * w0;
        acc.y += v0.y * w0;
        acc.z += v0.z * w0;
        acc.w += v0.w * w0;
    }
    reinterpret_cast<float4*>(out + (long long)node * 64)[lane] = acc;
}

extern "C" void kernel_launch(void* const* d_in, const int* in_sizes, int n_in,
                              void* d_out, int out_size)
{
    const float* feat = (const float*)d_in[0];
    const float* ew   = (const float*)d_in[1];
    const int*   esrc = (const int*)d_in[2];
    const int*   edst = (const int*)d_in[3];
    float*       out  = (float*)d_out;

    int n_edges = in_sizes[1];
    int n_nodes = out_size / 64;
    int nb      = (n_nodes + SCAN_CHUNK - 1) / SCAN_CHUNK;

    k_zero_cnt<<<(n_nodes + 255) / 256, 256>>>(n_nodes);
    k_hist<<<(n_edges + 255) / 256, 256>>>(esrc, n_edges);
    k_bsum<<<nb, 256>>>(n_nodes);
    k_scanb<<<1, 1>>>(nb);
    k_offsets<<<nb, SCAN_CHUNK>>>(n_nodes);
    k_scatter<<<(n_edges + 255) / 256, 256>>>(esrc, edst, ew, n_edges);

    long long total = (long long)n_nodes * 16;
    k_accum<<<(int)((total + 255) / 256), 256>>>(feat, out, n_nodes);
}